// round 14
// baseline (speedup 1.0000x reference)
#include <cuda_runtime.h>
#include <cuda_bf16.h>
#include <cuda_fp16.h>
#include <cstdint>
#include <math.h>

// ---------------------------------------------------------------------------
// QuantumLayer, SINGLE kernel: each CTA recomputes the 64-tap circulant
// generator + its HMMA B-fragment table in smem (kills the setup launch),
// then bf16-split HMMA matmul + threefry amplitude noise + L2 norm + abs.
// ---------------------------------------------------------------------------

#define DTOT 4096
#define CTAS 2048          // 2 tokens per CTA

// ------------------------- small helpers -----------------------------------
__device__ __forceinline__ unsigned pack_bf16x2(float lo_e, float hi_e) {
    unsigned r;
    asm("cvt.rn.bf16x2.f32 %0, %1, %2;" : "=r"(r) : "f"(hi_e), "f"(lo_e));
    return r;
}
__device__ __forceinline__ unsigned pack_f16x2(float lo_e, float hi_e) {
    unsigned r;
    asm("cvt.rn.f16x2.f32 %0, %1, %2;" : "=r"(r) : "f"(hi_e), "f"(lo_e));
    return r;
}
__device__ __forceinline__ void split2(float a, float b, unsigned &hi, unsigned &lo) {
    unsigned h = pack_bf16x2(a, b);
    float ha = __uint_as_float(h << 16);
    float hb = __uint_as_float(h & 0xffff0000u);
    hi = h;
    lo = pack_bf16x2(a - ha, b - hb);
}
#define HMMA(c0,c1,c2,c3,a,b0,b1)                                              \
    asm volatile("mma.sync.aligned.m16n8k16.row.col.f32.bf16.bf16.f32 "        \
        "{%0,%1,%2,%3}, {%4,%5,%6,%7}, {%8,%9}, {%0,%1,%2,%3};"                \
        : "+f"(c0), "+f"(c1), "+f"(c2), "+f"(c3)                               \
        : "r"((a)[0]), "r"((a)[1]), "r"((a)[2]), "r"((a)[3]), "r"(b0), "r"(b1))

// ------------------------- threefry2x32 (exact) ----------------------------
__host__ __device__ __forceinline__ unsigned rotl32(unsigned x, int r) {
#if defined(__CUDA_ARCH__)
    return __funnelshift_l(x, x, r);
#else
    return (x << r) | (x >> (32 - r));
#endif
}
__host__ __device__ __forceinline__ void threefry2x32(
    unsigned k0, unsigned k1, unsigned c0, unsigned c1, unsigned &y0, unsigned &y1)
{
    unsigned ks2 = k0 ^ k1 ^ 0x1BD11BDAu;
    unsigned x0 = c0 + k0;
    unsigned x1 = c1 + k1;
#define TF_R(r) { x0 += x1; x1 = rotl32(x1, (r)); x1 ^= x0; }
    TF_R(13) TF_R(15) TF_R(26) TF_R(6)
    x0 += k1;  x1 += ks2 + 1u;
    TF_R(17) TF_R(29) TF_R(16) TF_R(24)
    x0 += ks2; x1 += k0 + 2u;
    TF_R(13) TF_R(15) TF_R(26) TF_R(6)
    x0 += k0;  x1 += k1 + 3u;
    TF_R(17) TF_R(29) TF_R(16) TF_R(24)
    x0 += k1;  x1 += ks2 + 4u;
    TF_R(13) TF_R(15) TF_R(26) TF_R(6)
    x0 += ks2; x1 += k0 + 5u;
#undef TF_R
    y0 = x0; y1 = x1;
}

__device__ __forceinline__ float erfinv_approx(float x)
{
    float w = -__logf(fmaf(-x, x, 1.0f));
    float p;
    if (w < 5.0f) {
        w = w - 2.5f;
        p = 2.81022636e-08f;
        p = fmaf(p, w, 3.43273939e-07f);
        p = fmaf(p, w, -3.5233877e-06f);
        p = fmaf(p, w, -4.39150654e-06f);
        p = fmaf(p, w, 0.00021858087f);
        p = fmaf(p, w, -0.00125372503f);
        p = fmaf(p, w, -0.00417768164f);
        p = fmaf(p, w, 0.246640727f);
        p = fmaf(p, w, 1.50140941f);
    } else {
        w = sqrtf(w) - 3.0f;
        p = -0.000200214257f;
        p = fmaf(p, w, 0.000100950558f);
        p = fmaf(p, w, 0.00134934322f);
        p = fmaf(p, w, -0.00367342844f);
        p = fmaf(p, w, 0.00573950773f);
        p = fmaf(p, w, -0.0076224613f);
        p = fmaf(p, w, 0.00943887047f);
        p = fmaf(p, w, 1.00167406f);
        p = fmaf(p, w, 2.83297682f);
    }
    return p * x;
}
// delta = 0.01 * z  (noise multiplier = 1 + delta)
__device__ __forceinline__ float noise_delta(
    unsigned k0, unsigned k1, unsigned ks2, unsigned j)
{
    unsigned x0 = k0;
    unsigned x1 = j + k1;
#define TF_R(r) { x0 += x1; x1 = rotl32(x1, (r)); x1 ^= x0; }
    TF_R(13) TF_R(15) TF_R(26) TF_R(6)
    x0 += k1;  x1 += ks2 + 1u;
    TF_R(17) TF_R(29) TF_R(16) TF_R(24)
    x0 += ks2; x1 += k0 + 2u;
    TF_R(13) TF_R(15) TF_R(26) TF_R(6)
    x0 += k0;  x1 += k1 + 3u;
    TF_R(17) TF_R(29) TF_R(16) TF_R(24)
    x0 += k1;  x1 += ks2 + 4u;
    TF_R(13) TF_R(15) TF_R(26) TF_R(6)
    x0 += ks2; x1 += k0 + 5u;
#undef TF_R
    unsigned bits = x0 ^ x1;
    float v = (float)(bits >> 9);                       // exact I2F (23 bits)
    float u = fmaf(v, 2.3841858e-07f, -0.99999994f);    // jax uniform mapping
    float z = 1.41421354f * erfinv_approx(u);
    return 0.01f * z;
}

// ------------------------- main kernel (self-contained) ---------------------
__global__ void __launch_bounds__(256, 4)
quantum_main(const float* __restrict__ x,
             const float* __restrict__ rx,
             const float* __restrict__ ry,
             const float* __restrict__ rz,
             float* __restrict__ out,
             unsigned ka0, unsigned ka1)
{
    __shared__ __align__(16) uint2 Bf[2048];    // [img][j][kk][lane], 16KB
    __shared__ __align__(16) uint2 wsh[2048];   // fp16x2 staging [j][tid], 16KB
    // generator scratch (~2.4KB)
    __shared__ float c64[64], s64[64];
    __shared__ float cth[96], sthz[32];
    __shared__ float cvec[192];                 // cx | cy | cz
    __shared__ float hh[64], gg[64];
    __shared__ float red[8];

    const int tid = threadIdx.x;
    const int w   = tid >> 5;
    const int l   = tid & 31;
    const int t   = w >> 2;                   // token within CTA pair
    const int dg  = (w & 3) * 16 + (l >> 2);  // this thread's base d (row)
    const int blk = blockIdx.x;
    const unsigned ks2 = ka0 ^ ka1 ^ 0x1BD11BDAu;

    // --- phase 0: issue first-half X loads ---
    const float* xb = x + (size_t)(2 * blk + t) * DTOT + dg;
    float xv[16];
#pragma unroll
    for (int kk = 0; kk < 4; kk++) {
        const float* xp = xb + (kk * 16 + (l & 3) * 2) * 64;
        xv[kk * 4 + 0] = xp[0];
        xv[kk * 4 + 1] = xp[64];
        xv[kk * 4 + 2] = xp[8];
        xv[kk * 4 + 3] = xp[64 + 8];
    }

    // --- phase 1: generator (per-CTA recompute; barriers overlap cross-CTA) ---
    if (tid < 64) {
        c64[tid] = cospif((float)tid / 32.0f);
        s64[tid] = sinpif((float)tid / 32.0f);
    }
    if (tid < 96) {
        const float* rp = (tid < 32) ? rx : (tid < 64) ? ry : rz;
        int m = tid & 31;
        float sm = 0.0f;
        for (int j = 0; j < 16; j++) sm += rp[m * 16 + j];
        cth[tid] = cosf(0.5f * sm);
        if (tid >= 64) sthz[m] = sinf(0.5f * sm);
    }
    __syncthreads();
    if (tid < 192) {
        const int axis = tid >> 6;     // 0=x,1=y,2=z
        const int m = tid & 63;
        float a = 0.0f;
        for (int k = 0; k < 32; k++) {
            int n0 = (2 * k * m) & 63;
            int n1 = ((2 * k + 1) * m) & 63;
            float cc = c64[n0] + c64[n1];
            if (axis < 2) a = fmaf(cth[axis * 32 + k], cc, a);
            else          a = fmaf(cth[64 + k], cc, fmaf(sthz[k], s64[n0] - s64[n1], a));
        }
        cvec[tid] = a * (1.0f / 64.0f);
    }
    __syncthreads();
    if (tid < 64) {
        float acc = 0.0f;
        for (int s = 0; s < 64; s++) acc = fmaf(cvec[64 + s], cvec[(tid - s) & 63], acc);
        hh[tid] = acc;
    }
    __syncthreads();
    if (tid < 64) {
        float g = 0.0f;
        for (int s = 0; s < 64; s++) g = fmaf(cvec[128 + s], hh[(tid - s) & 63], g);
        gg[tid] = g;
    }
    __syncthreads();

    // --- phase 2: B-fragment table into smem (8 entries per thread) ---
#pragma unroll
    for (int e = tid; e < 2048; e += 256) {
        int lane = e & 31;
        int kk   = (e >> 5) & 3;
        int j    = (e >> 7) & 7;
        int img  = e >> 10;
        int p0 = kk * 16 + (lane & 3) * 2;
        int q  = j * 8 + (lane >> 2);
        float v0 = gg[(q - p0) & 63];
        float v1 = gg[(q - p0 - 1) & 63];
        float v2 = gg[(q - p0 - 8) & 63];
        float v3 = gg[(q - p0 - 9) & 63];
        unsigned h0, l0, h1, l1;
        split2(v0, v1, h0, l0);
        split2(v2, v3, h1, l1);
        Bf[e] = (img == 0) ? make_uint2(h0, h1) : make_uint2(l0, l1);
    }

    // --- phase 3: pure PRNG — 32 deltas into private smem slots ---
    const unsigned jb = (unsigned)((2 * blk + t) * DTOT) + (unsigned)dg;
#pragma unroll
    for (int j = 0; j < 8; j++) {
        const unsigned b = jb + (unsigned)(j * 8 + (l & 3) * 2) * 64u;
        float d0 = noise_delta(ka0, ka1, ks2, b);
        float d1 = noise_delta(ka0, ka1, ks2, b + 64u);
        float d2 = noise_delta(ka0, ka1, ks2, b + 8u);
        float d3 = noise_delta(ka0, ka1, ks2, b + 72u);
        wsh[j * 256 + tid] = make_uint2(pack_f16x2(d0, d1), pack_f16x2(d2, d3));
    }

    // --- phase 4: bf16-split A fragments (second-half X loads here) ---
    unsigned ahi[4][4], alo[4][4];
#pragma unroll
    for (int kk = 0; kk < 4; kk++) {
        const float* xp = xb + (kk * 16 + (l & 3) * 2) * 64;
        split2(xv[kk * 4 + 0], xv[kk * 4 + 1], ahi[kk][0], alo[kk][0]);
        split2(xv[kk * 4 + 2], xv[kk * 4 + 3], ahi[kk][1], alo[kk][1]);
        float v20 = xp[512], v21 = xp[576];
        float v30 = xp[512 + 8], v31 = xp[576 + 8];
        split2(v20, v21, ahi[kk][2], alo[kk][2]);
        split2(v30, v31, ahi[kk][3], alo[kk][3]);
    }

    __syncthreads();   // Bf complete (phase 2) before matmul reads it

    // --- phase 5: 8 n-tiles, 12 HMMAs as two 6-chains; apply deltas ---
    float s = 0.0f;
#pragma unroll
    for (int j = 0; j < 8; j++) {
        float c0 = 0.f, c1 = 0.f, c2 = 0.f, c3 = 0.f;   // chain 1
        float d0 = 0.f, d1 = 0.f, d2 = 0.f, d3 = 0.f;   // chain 2
#pragma unroll
        for (int kk = 0; kk < 4; kk++) {
            uint2 bh = Bf[(j * 4 + kk) * 32 + l];
            uint2 bl = Bf[1024 + (j * 4 + kk) * 32 + l];
            HMMA(c0, c1, c2, c3, ahi[kk], bh.x, bh.y);
            HMMA(d0, d1, d2, d3, ahi[kk], bl.x, bl.y);
            if (kk < 2) { HMMA(c0, c1, c2, c3, alo[kk], bh.x, bh.y); }
            else        { HMMA(d0, d1, d2, d3, alo[kk], bh.x, bh.y); }
        }
        uint2 pv = wsh[j * 256 + tid];
        float2 n01 = __half22float2(*reinterpret_cast<const __half2*>(&pv.x));
        float2 n23 = __half22float2(*reinterpret_cast<const __half2*>(&pv.y));
        float y0 = c0 + d0, y1 = c1 + d1, y2 = c2 + d2, y3 = c3 + d3;
        float w0 = fmaf(y0, n01.x, y0);
        float w1 = fmaf(y1, n01.y, y1);
        float w2 = fmaf(y2, n23.x, y2);
        float w3 = fmaf(y3, n23.y, y3);
        s = fmaf(w0, w0, fmaf(w1, w1, fmaf(w2, w2, fmaf(w3, w3, s))));
        wsh[j * 256 + tid] = make_uint2(pack_f16x2(w0, w1), pack_f16x2(w2, w3));
    }

    // --- per-token norm: warp reduce + 4 warps per token via smem ---
#pragma unroll
    for (int off = 16; off > 0; off >>= 1)
        s += __shfl_xor_sync(0xffffffffu, s, off);
    if (l == 0) red[w] = s;
    __syncthreads();
    const float S = red[t * 4] + red[t * 4 + 1] + red[t * 4 + 2] + red[t * 4 + 3];
    const float inv = __fdividef(1.0f, sqrtf(S) + 1e-8f);

    // --- read own staged fp16 values, finalize |w| * inv, store once ---
    float* o = out + (size_t)(2 * blk + t) * DTOT + dg;
#pragma unroll
    for (int j = 0; j < 8; j++) {
        uint2 pv = wsh[j * 256 + tid];
        float2 f01 = __half22float2(*reinterpret_cast<const __half2*>(&pv.x));
        float2 f23 = __half22float2(*reinterpret_cast<const __half2*>(&pv.y));
        const int qe = j * 8 + (l & 3) * 2;
        float* oj = o + qe * 64;
        __stcg(oj,      fabsf(f01.x) * inv);
        __stcg(oj + 64, fabsf(f01.y) * inv);
        __stcg(oj + 8,  fabsf(f23.x) * inv);
        __stcg(oj + 72, fabsf(f23.y) * inv);
    }
}

// ------------------------- launch ------------------------------------------
extern "C" void kernel_launch(void* const* d_in, const int* in_sizes, int n_in,
                              void* d_out, int out_size)
{
    const float* x  = (const float*)d_in[0];
    const float* rx = (const float*)d_in[1];
    const float* ry = (const float*)d_in[2];
    const float* rz = (const float*)d_in[3];
    float* out = (float*)d_out;

    unsigned ka0, ka1;
    threefry2x32(0u, 42u, 0u, 0u, ka0, ka1);

    quantum_main<<<CTAS, 256>>>(x, rx, ry, rz, out, ka0, ka1);
}

// round 15
// speedup vs baseline: 1.2200x; 1.2200x over previous
#include <cuda_runtime.h>
#include <cuda_bf16.h>
#include <cuda_fp16.h>
#include <cstdint>
#include <math.h>

// ---------------------------------------------------------------------------
// QuantumLayer, single launch: block 0 computes the 64-tap circulant
// generator -> HMMA B-fragment table (global), sets a flag; all other CTAs
// overlap their PRNG/X-load phases with that setup, then spin briefly and
// proceed. Flag is reset by the last CTA each launch (self-contained).
// Math: bf16-split mma.sync HMMA + threefry amplitude noise + L2 norm + abs.
// ---------------------------------------------------------------------------

#define DTOT 4096
#define CTAS 2048          // 2 tokens per CTA

__device__ uint2 d_Bfrag[2048];   // [img(hi,lo)][j(8)][kk(4)][lane(32)]
__device__ int      g_flag = 0;   // setup-done flag (reset at end of launch)
__device__ unsigned g_done = 0;   // CTA completion counter

// ------------------------- small helpers -----------------------------------
__device__ __forceinline__ unsigned smem_u32(const void* p) {
    unsigned a;
    asm("{ .reg .u64 t; cvta.to.shared.u64 t, %1; cvt.u32.u64 %0, t; }" : "=r"(a) : "l"(p));
    return a;
}
__device__ __forceinline__ void cp_async16(void* s, const void* g) {
    asm volatile("cp.async.ca.shared.global [%0], [%1], 16;" :: "r"(smem_u32(s)), "l"(g));
}
__device__ __forceinline__ unsigned pack_bf16x2(float lo_e, float hi_e) {
    unsigned r;
    asm("cvt.rn.bf16x2.f32 %0, %1, %2;" : "=r"(r) : "f"(hi_e), "f"(lo_e));
    return r;
}
__device__ __forceinline__ unsigned pack_f16x2(float lo_e, float hi_e) {
    unsigned r;
    asm("cvt.rn.f16x2.f32 %0, %1, %2;" : "=r"(r) : "f"(hi_e), "f"(lo_e));
    return r;
}
__device__ __forceinline__ void split2(float a, float b, unsigned &hi, unsigned &lo) {
    unsigned h = pack_bf16x2(a, b);
    float ha = __uint_as_float(h << 16);
    float hb = __uint_as_float(h & 0xffff0000u);
    hi = h;
    lo = pack_bf16x2(a - ha, b - hb);
}
#define HMMA(c0,c1,c2,c3,a,b0,b1)                                              \
    asm volatile("mma.sync.aligned.m16n8k16.row.col.f32.bf16.bf16.f32 "        \
        "{%0,%1,%2,%3}, {%4,%5,%6,%7}, {%8,%9}, {%0,%1,%2,%3};"                \
        : "+f"(c0), "+f"(c1), "+f"(c2), "+f"(c3)                               \
        : "r"((a)[0]), "r"((a)[1]), "r"((a)[2]), "r"((a)[3]), "r"(b0), "r"(b1))

// ------------------------- threefry2x32 (exact) ----------------------------
__host__ __device__ __forceinline__ unsigned rotl32(unsigned x, int r) {
#if defined(__CUDA_ARCH__)
    return __funnelshift_l(x, x, r);
#else
    return (x << r) | (x >> (32 - r));
#endif
}
__host__ __device__ __forceinline__ void threefry2x32(
    unsigned k0, unsigned k1, unsigned c0, unsigned c1, unsigned &y0, unsigned &y1)
{
    unsigned ks2 = k0 ^ k1 ^ 0x1BD11BDAu;
    unsigned x0 = c0 + k0;
    unsigned x1 = c1 + k1;
#define TF_R(r) { x0 += x1; x1 = rotl32(x1, (r)); x1 ^= x0; }
    TF_R(13) TF_R(15) TF_R(26) TF_R(6)
    x0 += k1;  x1 += ks2 + 1u;
    TF_R(17) TF_R(29) TF_R(16) TF_R(24)
    x0 += ks2; x1 += k0 + 2u;
    TF_R(13) TF_R(15) TF_R(26) TF_R(6)
    x0 += k0;  x1 += k1 + 3u;
    TF_R(17) TF_R(29) TF_R(16) TF_R(24)
    x0 += k1;  x1 += ks2 + 4u;
    TF_R(13) TF_R(15) TF_R(26) TF_R(6)
    x0 += ks2; x1 += k0 + 5u;
#undef TF_R
    y0 = x0; y1 = x1;
}

__device__ __forceinline__ float erfinv_approx(float x)
{
    float w = -__logf(fmaf(-x, x, 1.0f));
    float p;
    if (w < 5.0f) {
        w = w - 2.5f;
        p = 2.81022636e-08f;
        p = fmaf(p, w, 3.43273939e-07f);
        p = fmaf(p, w, -3.5233877e-06f);
        p = fmaf(p, w, -4.39150654e-06f);
        p = fmaf(p, w, 0.00021858087f);
        p = fmaf(p, w, -0.00125372503f);
        p = fmaf(p, w, -0.00417768164f);
        p = fmaf(p, w, 0.246640727f);
        p = fmaf(p, w, 1.50140941f);
    } else {
        w = sqrtf(w) - 3.0f;
        p = -0.000200214257f;
        p = fmaf(p, w, 0.000100950558f);
        p = fmaf(p, w, 0.00134934322f);
        p = fmaf(p, w, -0.00367342844f);
        p = fmaf(p, w, 0.00573950773f);
        p = fmaf(p, w, -0.0076224613f);
        p = fmaf(p, w, 0.00943887047f);
        p = fmaf(p, w, 1.00167406f);
        p = fmaf(p, w, 2.83297682f);
    }
    return p * x;
}
// delta = 0.01 * z  (noise multiplier = 1 + delta)
__device__ __forceinline__ float noise_delta(
    unsigned k0, unsigned k1, unsigned ks2, unsigned j)
{
    unsigned x0 = k0;
    unsigned x1 = j + k1;
#define TF_R(r) { x0 += x1; x1 = rotl32(x1, (r)); x1 ^= x0; }
    TF_R(13) TF_R(15) TF_R(26) TF_R(6)
    x0 += k1;  x1 += ks2 + 1u;
    TF_R(17) TF_R(29) TF_R(16) TF_R(24)
    x0 += ks2; x1 += k0 + 2u;
    TF_R(13) TF_R(15) TF_R(26) TF_R(6)
    x0 += k0;  x1 += k1 + 3u;
    TF_R(17) TF_R(29) TF_R(16) TF_R(24)
    x0 += k1;  x1 += ks2 + 4u;
    TF_R(13) TF_R(15) TF_R(26) TF_R(6)
    x0 += ks2; x1 += k0 + 5u;
#undef TF_R
    unsigned bits = x0 ^ x1;
    float v = (float)(bits >> 9);                       // exact I2F (23 bits)
    float u = fmaf(v, 2.3841858e-07f, -0.99999994f);    // jax uniform mapping
    float z = 1.41421354f * erfinv_approx(u);
    return 0.01f * z;
}

// ------------------------- main kernel --------------------------------------
__global__ void __launch_bounds__(256, 4)
quantum_main(const float* __restrict__ x,
             const float* __restrict__ rx,
             const float* __restrict__ ry,
             const float* __restrict__ rz,
             float* __restrict__ out,
             unsigned ka0, unsigned ka1)
{
    __shared__ __align__(16) uint2 Bf[2048];    // [img][j][kk][lane], 16KB
    __shared__ __align__(16) uint2 wsh[2048];   // fp16x2 staging [j][tid], 16KB
    __shared__ float red[8];

    const int tid = threadIdx.x;
    const int w   = tid >> 5;
    const int l   = tid & 31;
    const int t   = w >> 2;                   // token within CTA pair
    const int dg  = (w & 3) * 16 + (l >> 2);  // this thread's base d (row)
    const int blk = blockIdx.x;
    const unsigned ks2 = ka0 ^ ka1 ^ 0x1BD11BDAu;

    // === block 0 only: compute generator + B-fragment table, publish ===
    if (blk == 0) {
        __shared__ float c64[64], s64[64];
        __shared__ float cth[96], sthz[32];
        __shared__ float cvec[192];
        __shared__ float hh[64], gg[64];

        if (tid < 64) {
            c64[tid] = cospif((float)tid / 32.0f);
            s64[tid] = sinpif((float)tid / 32.0f);
        }
        if (tid < 96) {
            const float* rp = (tid < 32) ? rx : (tid < 64) ? ry : rz;
            int m = tid & 31;
            float sm = 0.0f;
            for (int j = 0; j < 16; j++) sm += rp[m * 16 + j];
            cth[tid] = cosf(0.5f * sm);
            if (tid >= 64) sthz[m] = sinf(0.5f * sm);
        }
        __syncthreads();
        if (tid < 192) {
            const int axis = tid >> 6;
            const int m = tid & 63;
            float a = 0.0f;
            for (int k = 0; k < 32; k++) {
                int n0 = (2 * k * m) & 63;
                int n1 = ((2 * k + 1) * m) & 63;
                float cc = c64[n0] + c64[n1];
                if (axis < 2) a = fmaf(cth[axis * 32 + k], cc, a);
                else          a = fmaf(cth[64 + k], cc, fmaf(sthz[k], s64[n0] - s64[n1], a));
            }
            cvec[tid] = a * (1.0f / 64.0f);
        }
        __syncthreads();
        if (tid < 64) {
            float acc = 0.0f;
            for (int s = 0; s < 64; s++) acc = fmaf(cvec[64 + s], cvec[(tid - s) & 63], acc);
            hh[tid] = acc;
        }
        __syncthreads();
        if (tid < 64) {
            float g = 0.0f;
            for (int s = 0; s < 64; s++) g = fmaf(cvec[128 + s], hh[(tid - s) & 63], g);
            gg[tid] = g;
        }
        __syncthreads();
#pragma unroll
        for (int e = tid; e < 2048; e += 256) {
            int lane = e & 31;
            int kk   = (e >> 5) & 3;
            int j    = (e >> 7) & 7;
            int img  = e >> 10;
            int p0 = kk * 16 + (lane & 3) * 2;
            int q  = j * 8 + (lane >> 2);
            float v0 = gg[(q - p0) & 63];
            float v1 = gg[(q - p0 - 1) & 63];
            float v2 = gg[(q - p0 - 8) & 63];
            float v3 = gg[(q - p0 - 9) & 63];
            unsigned h0, l0, h1, l1;
            split2(v0, v1, h0, l0);
            split2(v2, v3, h1, l1);
            uint2 fr = (img == 0) ? make_uint2(h0, h1) : make_uint2(l0, l1);
            Bf[e] = fr;
            d_Bfrag[e] = fr;
        }
        __threadfence();
        __syncthreads();
        if (tid == 0) atomicExch(&g_flag, 1);
    }

    // === all blocks: Bfrag-independent phases ===
    // phase 0: first-half X loads
    const float* xb = x + (size_t)(2 * blk + t) * DTOT + dg;
    float xv[16];
#pragma unroll
    for (int kk = 0; kk < 4; kk++) {
        const float* xp = xb + (kk * 16 + (l & 3) * 2) * 64;
        xv[kk * 4 + 0] = xp[0];
        xv[kk * 4 + 1] = xp[64];
        xv[kk * 4 + 2] = xp[8];
        xv[kk * 4 + 3] = xp[64 + 8];
    }

    // phase 1: pure PRNG — 32 deltas into private smem slots
    const unsigned jb = (unsigned)((2 * blk + t) * DTOT) + (unsigned)dg;
#pragma unroll
    for (int j = 0; j < 8; j++) {
        const unsigned b = jb + (unsigned)(j * 8 + (l & 3) * 2) * 64u;
        float d0 = noise_delta(ka0, ka1, ks2, b);
        float d1 = noise_delta(ka0, ka1, ks2, b + 64u);
        float d2 = noise_delta(ka0, ka1, ks2, b + 8u);
        float d3 = noise_delta(ka0, ka1, ks2, b + 72u);
        wsh[j * 256 + tid] = make_uint2(pack_f16x2(d0, d1), pack_f16x2(d2, d3));
    }

    // phase 2: bf16-split A fragments (second-half X loads here)
    unsigned ahi[4][4], alo[4][4];
#pragma unroll
    for (int kk = 0; kk < 4; kk++) {
        const float* xp = xb + (kk * 16 + (l & 3) * 2) * 64;
        split2(xv[kk * 4 + 0], xv[kk * 4 + 1], ahi[kk][0], alo[kk][0]);
        split2(xv[kk * 4 + 2], xv[kk * 4 + 3], ahi[kk][1], alo[kk][1]);
        float v20 = xp[512], v21 = xp[576];
        float v30 = xp[512 + 8], v31 = xp[576 + 8];
        split2(v20, v21, ahi[kk][2], alo[kk][2]);
        split2(v30, v31, ahi[kk][3], alo[kk][3]);
    }

    // phase 3: non-zero blocks wait for setup, then fetch B fragments
    if (blk != 0) {
        if (tid == 0) {
            while (*(volatile int*)&g_flag == 0) __nanosleep(64);
        }
        __syncthreads();
        __threadfence();    // acquire: d_Bfrag writes visible
#pragma unroll
        for (int i = 0; i < 4; i++)
            cp_async16(&Bf[tid * 8 + i * 2], &d_Bfrag[tid * 8 + i * 2]);
        asm volatile("cp.async.commit_group;");
        asm volatile("cp.async.wait_group 0;");
    }
    __syncthreads();   // Bf complete before matmul reads it

    // phase 4: 8 n-tiles, 12 HMMAs as two 6-chains; apply deltas
    float s = 0.0f;
#pragma unroll
    for (int j = 0; j < 8; j++) {
        float c0 = 0.f, c1 = 0.f, c2 = 0.f, c3 = 0.f;   // chain 1
        float d0 = 0.f, d1 = 0.f, d2 = 0.f, d3 = 0.f;   // chain 2
#pragma unroll
        for (int kk = 0; kk < 4; kk++) {
            uint2 bh = Bf[(j * 4 + kk) * 32 + l];
            uint2 bl = Bf[1024 + (j * 4 + kk) * 32 + l];
            HMMA(c0, c1, c2, c3, ahi[kk], bh.x, bh.y);
            HMMA(d0, d1, d2, d3, ahi[kk], bl.x, bl.y);
            if (kk < 2) { HMMA(c0, c1, c2, c3, alo[kk], bh.x, bh.y); }
            else        { HMMA(d0, d1, d2, d3, alo[kk], bh.x, bh.y); }
        }
        uint2 pv = wsh[j * 256 + tid];
        float2 n01 = __half22float2(*reinterpret_cast<const __half2*>(&pv.x));
        float2 n23 = __half22float2(*reinterpret_cast<const __half2*>(&pv.y));
        float y0 = c0 + d0, y1 = c1 + d1, y2 = c2 + d2, y3 = c3 + d3;
        float w0 = fmaf(y0, n01.x, y0);
        float w1 = fmaf(y1, n01.y, y1);
        float w2 = fmaf(y2, n23.x, y2);
        float w3 = fmaf(y3, n23.y, y3);
        s = fmaf(w0, w0, fmaf(w1, w1, fmaf(w2, w2, fmaf(w3, w3, s))));
        wsh[j * 256 + tid] = make_uint2(pack_f16x2(w0, w1), pack_f16x2(w2, w3));
    }

    // per-token norm
#pragma unroll
    for (int off = 16; off > 0; off >>= 1)
        s += __shfl_xor_sync(0xffffffffu, s, off);
    if (l == 0) red[w] = s;
    __syncthreads();
    const float S = red[t * 4] + red[t * 4 + 1] + red[t * 4 + 2] + red[t * 4 + 3];
    const float inv = __fdividef(1.0f, sqrtf(S) + 1e-8f);

    // finalize |w| * inv, store
    float* o = out + (size_t)(2 * blk + t) * DTOT + dg;
#pragma unroll
    for (int j = 0; j < 8; j++) {
        uint2 pv = wsh[j * 256 + tid];
        float2 f01 = __half22float2(*reinterpret_cast<const __half2*>(&pv.x));
        float2 f23 = __half22float2(*reinterpret_cast<const __half2*>(&pv.y));
        const int qe = j * 8 + (l & 3) * 2;
        float* oj = o + qe * 64;
        __stcg(oj,      fabsf(f01.x) * inv);
        __stcg(oj + 64, fabsf(f01.y) * inv);
        __stcg(oj + 8,  fabsf(f23.x) * inv);
        __stcg(oj + 72, fabsf(f23.y) * inv);
    }

    // self-contained flag reset: last CTA to finish clears state for the
    // next launch (every launch waits on ITS OWN setup — no caching).
    if (tid == 0) {
        unsigned old = atomicAdd(&g_done, 1u);
        if (old == CTAS - 1) {
            g_done = 0;
            __threadfence();
            atomicExch(&g_flag, 0);
        }
    }
}

// ------------------------- launch ------------------------------------------
extern "C" void kernel_launch(void* const* d_in, const int* in_sizes, int n_in,
                              void* d_out, int out_size)
{
    const float* x  = (const float*)d_in[0];
    const float* rx = (const float*)d_in[1];
    const float* ry = (const float*)d_in[2];
    const float* rz = (const float*)d_in[3];
    float* out = (float*)d_out;

    unsigned ka0, ka1;
    threefry2x32(0u, 42u, 0u, 0u, ka0, ka1);

    quantum_main<<<CTAS, 256>>>(x, rx, ry, rz, out, ka0, ka1);
}

// round 16
// speedup vs baseline: 1.2528x; 1.0269x over previous
#include <cuda_runtime.h>
#include <cuda_bf16.h>
#include <cuda_fp16.h>
#include <cstdint>
#include <math.h>

// ---------------------------------------------------------------------------
// QuantumLayer, single launch: block 0 computes the 64-tap circulant
// generator -> HMMA B-fragment table (global), sets a flag; other CTAs
// opportunistically fetch the table early (flag already set for waves>=2),
// else overlap PRNG with the wait. bf16-split mma.sync HMMA + threefry
// amplitude noise (scaled-coefficient erfinv) + L2 norm + abs.
// ---------------------------------------------------------------------------

#define DTOT 4096
#define CTAS 2048          // 2 tokens per CTA

__device__ uint2 d_Bfrag[2048];   // [img(hi,lo)][j(8)][kk(4)][lane(32)]
__device__ int      g_flag = 0;   // setup-done flag (reset at end of launch)
__device__ unsigned g_done = 0;   // CTA completion counter

// ------------------------- small helpers -----------------------------------
__device__ __forceinline__ unsigned smem_u32(const void* p) {
    unsigned a;
    asm("{ .reg .u64 t; cvta.to.shared.u64 t, %1; cvt.u32.u64 %0, t; }" : "=r"(a) : "l"(p));
    return a;
}
__device__ __forceinline__ void cp_async16(void* s, const void* g) {
    asm volatile("cp.async.ca.shared.global [%0], [%1], 16;" :: "r"(smem_u32(s)), "l"(g));
}
__device__ __forceinline__ unsigned pack_bf16x2(float lo_e, float hi_e) {
    unsigned r;
    asm("cvt.rn.bf16x2.f32 %0, %1, %2;" : "=r"(r) : "f"(hi_e), "f"(lo_e));
    return r;
}
__device__ __forceinline__ unsigned pack_f16x2(float lo_e, float hi_e) {
    unsigned r;
    asm("cvt.rn.f16x2.f32 %0, %1, %2;" : "=r"(r) : "f"(hi_e), "f"(lo_e));
    return r;
}
__device__ __forceinline__ void split2(float a, float b, unsigned &hi, unsigned &lo) {
    unsigned h = pack_bf16x2(a, b);
    float ha = __uint_as_float(h << 16);
    float hb = __uint_as_float(h & 0xffff0000u);
    hi = h;
    lo = pack_bf16x2(a - ha, b - hb);
}
#define HMMA(c0,c1,c2,c3,a,b0,b1)                                              \
    asm volatile("mma.sync.aligned.m16n8k16.row.col.f32.bf16.bf16.f32 "        \
        "{%0,%1,%2,%3}, {%4,%5,%6,%7}, {%8,%9}, {%0,%1,%2,%3};"                \
        : "+f"(c0), "+f"(c1), "+f"(c2), "+f"(c3)                               \
        : "r"((a)[0]), "r"((a)[1]), "r"((a)[2]), "r"((a)[3]), "r"(b0), "r"(b1))

// ------------------------- threefry2x32 (exact) ----------------------------
__host__ __device__ __forceinline__ unsigned rotl32(unsigned x, int r) {
#if defined(__CUDA_ARCH__)
    return __funnelshift_l(x, x, r);
#else
    return (x << r) | (x >> (32 - r));
#endif
}
__host__ __device__ __forceinline__ void threefry2x32(
    unsigned k0, unsigned k1, unsigned c0, unsigned c1, unsigned &y0, unsigned &y1)
{
    unsigned ks2 = k0 ^ k1 ^ 0x1BD11BDAu;
    unsigned x0 = c0 + k0;
    unsigned x1 = c1 + k1;
#define TF_R(r) { x0 += x1; x1 = rotl32(x1, (r)); x1 ^= x0; }
    TF_R(13) TF_R(15) TF_R(26) TF_R(6)
    x0 += k1;  x1 += ks2 + 1u;
    TF_R(17) TF_R(29) TF_R(16) TF_R(24)
    x0 += ks2; x1 += k0 + 2u;
    TF_R(13) TF_R(15) TF_R(26) TF_R(6)
    x0 += k0;  x1 += k1 + 3u;
    TF_R(17) TF_R(29) TF_R(16) TF_R(24)
    x0 += k1;  x1 += ks2 + 4u;
    TF_R(13) TF_R(15) TF_R(26) TF_R(6)
    x0 += ks2; x1 += k0 + 5u;
#undef TF_R
    y0 = x0; y1 = x1;
}

// erfinv poly with coefficients pre-scaled by 0.01*sqrt(2): returns DELTA
// (= 0.01 * z) directly as p(w)*x.
__device__ __forceinline__ float erfinv_delta(float x)
{
    float w = -__logf(fmaf(-x, x, 1.0f));
    float p;
    if (w < 5.0f) {
        w = w - 2.5f;
        p = 3.97430e-10f;
        p = fmaf(p, w, 4.85464e-09f);
        p = fmaf(p, w, -4.98282e-08f);
        p = fmaf(p, w, -6.21053e-08f);
        p = fmaf(p, w, 3.09121e-06f);
        p = fmaf(p, w, -1.77304e-05f);
        p = fmaf(p, w, -5.90814e-05f);
        p = fmaf(p, w, 3.48803e-03f);
        p = fmaf(p, w, 2.12332e-02f);
    } else {
        w = sqrtf(w) - 3.0f;
        p = -2.83146e-06f;
        p = fmaf(p, w, 1.42766e-06f);
        p = fmaf(p, w, 1.90827e-05f);
        p = fmaf(p, w, -5.19502e-05f);
        p = fmaf(p, w, 8.11688e-05f);
        p = fmaf(p, w, -1.07799e-04f);
        p = fmaf(p, w, 1.33486e-04f);
        p = fmaf(p, w, 1.41658e-02f);
        p = fmaf(p, w, 4.00645e-02f);
    }
    return p * x;
}
// delta = 0.01 * z  (noise multiplier = 1 + delta)
__device__ __forceinline__ float noise_delta(
    unsigned k0, unsigned k1, unsigned ks2, unsigned j)
{
    unsigned x0 = k0;
    unsigned x1 = j + k1;
#define TF_R(r) { x0 += x1; x1 = rotl32(x1, (r)); x1 ^= x0; }
    TF_R(13) TF_R(15) TF_R(26) TF_R(6)
    x0 += k1;  x1 += ks2 + 1u;
    TF_R(17) TF_R(29) TF_R(16) TF_R(24)
    x0 += ks2; x1 += k0 + 2u;
    TF_R(13) TF_R(15) TF_R(26) TF_R(6)
    x0 += k0;  x1 += k1 + 3u;
    TF_R(17) TF_R(29) TF_R(16) TF_R(24)
    x0 += k1;  x1 += ks2 + 4u;
    TF_R(13) TF_R(15) TF_R(26) TF_R(6)
    x0 += ks2; x1 += k0 + 5u;
#undef TF_R
    unsigned bits = x0 ^ x1;
    float v = (float)(bits >> 9);                       // exact I2F (23 bits)
    float u = fmaf(v, 2.3841858e-07f, -0.99999994f);    // jax uniform mapping
    return erfinv_delta(u);
}

// ------------------------- main kernel --------------------------------------
__global__ void __launch_bounds__(256, 4)
quantum_main(const float* __restrict__ x,
             const float* __restrict__ rx,
             const float* __restrict__ ry,
             const float* __restrict__ rz,
             float* __restrict__ out,
             unsigned ka0, unsigned ka1)
{
    __shared__ __align__(16) uint2 Bf[2048];    // [img][j][kk][lane], 16KB
    __shared__ __align__(16) uint2 wsh[2048];   // fp16x2 staging [j][tid], 16KB
    __shared__ float red[8];

    const int tid = threadIdx.x;
    const int w   = tid >> 5;
    const int l   = tid & 31;
    const int t   = w >> 2;                   // token within CTA pair
    const int dg  = (w & 3) * 16 + (l >> 2);  // this thread's base d (row)
    const int blk = blockIdx.x;
    const unsigned ks2 = ka0 ^ ka1 ^ 0x1BD11BDAu;

    // === block 0 only: compute generator + B-fragment table, publish ===
    if (blk == 0) {
        __shared__ float c64[64], s64[64];
        __shared__ float cth[96], sthz[32];
        __shared__ float cvec[192];
        __shared__ float hh[64], gg[64];

        if (tid < 64) {
            c64[tid] = cospif((float)tid / 32.0f);
            s64[tid] = sinpif((float)tid / 32.0f);
        }
        if (tid < 96) {
            const float* rp = (tid < 32) ? rx : (tid < 64) ? ry : rz;
            int m = tid & 31;
            float sm = 0.0f;
            for (int j = 0; j < 16; j++) sm += rp[m * 16 + j];
            cth[tid] = cosf(0.5f * sm);
            if (tid >= 64) sthz[m] = sinf(0.5f * sm);
        }
        __syncthreads();
        if (tid < 192) {
            const int axis = tid >> 6;
            const int m = tid & 63;
            float a = 0.0f;
            for (int k = 0; k < 32; k++) {
                int n0 = (2 * k * m) & 63;
                int n1 = ((2 * k + 1) * m) & 63;
                float cc = c64[n0] + c64[n1];
                if (axis < 2) a = fmaf(cth[axis * 32 + k], cc, a);
                else          a = fmaf(cth[64 + k], cc, fmaf(sthz[k], s64[n0] - s64[n1], a));
            }
            cvec[tid] = a * (1.0f / 64.0f);
        }
        __syncthreads();
        if (tid < 64) {
            float acc = 0.0f;
            for (int s = 0; s < 64; s++) acc = fmaf(cvec[64 + s], cvec[(tid - s) & 63], acc);
            hh[tid] = acc;
        }
        __syncthreads();
        if (tid < 64) {
            float g = 0.0f;
            for (int s = 0; s < 64; s++) g = fmaf(cvec[128 + s], hh[(tid - s) & 63], g);
            gg[tid] = g;
        }
        __syncthreads();
#pragma unroll
        for (int e = tid; e < 2048; e += 256) {
            int lane = e & 31;
            int kk   = (e >> 5) & 3;
            int j    = (e >> 7) & 7;
            int img  = e >> 10;
            int p0 = kk * 16 + (lane & 3) * 2;
            int q  = j * 8 + (lane >> 2);
            float v0 = gg[(q - p0) & 63];
            float v1 = gg[(q - p0 - 1) & 63];
            float v2 = gg[(q - p0 - 8) & 63];
            float v3 = gg[(q - p0 - 9) & 63];
            unsigned h0, l0, h1, l1;
            split2(v0, v1, h0, l0);
            split2(v2, v3, h1, l1);
            uint2 fr = (img == 0) ? make_uint2(h0, h1) : make_uint2(l0, l1);
            Bf[e] = fr;
            d_Bfrag[e] = fr;
        }
        __threadfence();
        __syncthreads();
        if (tid == 0) atomicExch(&g_flag, 1);
    }

    // === other blocks: opportunistic early B-fragment fetch ===
    bool early = false;
    if (blk != 0) {
        int rdy = *(volatile int*)&g_flag;
        early = __all_sync(0xffffffffu, rdy != 0);
        if (early) {
#pragma unroll
            for (int i = 0; i < 4; i++)
                cp_async16(&Bf[tid * 8 + i * 2], &d_Bfrag[tid * 8 + i * 2]);
            asm volatile("cp.async.commit_group;");
        }
    }

    // === all blocks: Bfrag-independent phases ===
    // phase 0: first-half X loads
    const float* xb = x + (size_t)(2 * blk + t) * DTOT + dg;
    float xv[16];
#pragma unroll
    for (int kk = 0; kk < 4; kk++) {
        const float* xp = xb + (kk * 16 + (l & 3) * 2) * 64;
        xv[kk * 4 + 0] = xp[0];
        xv[kk * 4 + 1] = xp[64];
        xv[kk * 4 + 2] = xp[8];
        xv[kk * 4 + 3] = xp[64 + 8];
    }

    // phase 1: pure PRNG — 32 deltas into private smem slots
    const unsigned jb = (unsigned)((2 * blk + t) * DTOT) + (unsigned)dg;
#pragma unroll
    for (int j = 0; j < 8; j++) {
        const unsigned b = jb + (unsigned)(j * 8 + (l & 3) * 2) * 64u;
        float d0 = noise_delta(ka0, ka1, ks2, b);
        float d1 = noise_delta(ka0, ka1, ks2, b + 64u);
        float d2 = noise_delta(ka0, ka1, ks2, b + 8u);
        float d3 = noise_delta(ka0, ka1, ks2, b + 72u);
        wsh[j * 256 + tid] = make_uint2(pack_f16x2(d0, d1), pack_f16x2(d2, d3));
    }

    // phase 2: bf16-split A fragments (second-half X loads here)
    unsigned ahi[4][4], alo[4][4];
#pragma unroll
    for (int kk = 0; kk < 4; kk++) {
        const float* xp = xb + (kk * 16 + (l & 3) * 2) * 64;
        split2(xv[kk * 4 + 0], xv[kk * 4 + 1], ahi[kk][0], alo[kk][0]);
        split2(xv[kk * 4 + 2], xv[kk * 4 + 3], ahi[kk][1], alo[kk][1]);
        float v20 = xp[512], v21 = xp[576];
        float v30 = xp[512 + 8], v31 = xp[576 + 8];
        split2(v20, v21, ahi[kk][2], alo[kk][2]);
        split2(v30, v31, ahi[kk][3], alo[kk][3]);
    }

    // phase 3: late path — wait for setup then fetch B fragments (per-warp)
    if (blk != 0 && !early) {
        if (l == 0) {
            while (*(volatile int*)&g_flag == 0) __nanosleep(64);
        }
        __syncwarp();
#pragma unroll
        for (int i = 0; i < 4; i++)
            cp_async16(&Bf[tid * 8 + i * 2], &d_Bfrag[tid * 8 + i * 2]);
        asm volatile("cp.async.commit_group;");
    }
    asm volatile("cp.async.wait_group 0;");
    __syncthreads();   // all warps' Bf slices complete before matmul

    // phase 4: 8 n-tiles, 12 HMMAs as two 6-chains; apply deltas
    float s = 0.0f;
#pragma unroll
    for (int j = 0; j < 8; j++) {
        float c0 = 0.f, c1 = 0.f, c2 = 0.f, c3 = 0.f;   // chain 1
        float d0 = 0.f, d1 = 0.f, d2 = 0.f, d3 = 0.f;   // chain 2
#pragma unroll
        for (int kk = 0; kk < 4; kk++) {
            uint2 bh = Bf[(j * 4 + kk) * 32 + l];
            uint2 bl = Bf[1024 + (j * 4 + kk) * 32 + l];
            HMMA(c0, c1, c2, c3, ahi[kk], bh.x, bh.y);
            HMMA(d0, d1, d2, d3, ahi[kk], bl.x, bl.y);
            if (kk < 2) { HMMA(c0, c1, c2, c3, alo[kk], bh.x, bh.y); }
            else        { HMMA(d0, d1, d2, d3, alo[kk], bh.x, bh.y); }
        }
        uint2 pv = wsh[j * 256 + tid];
        float2 n01 = __half22float2(*reinterpret_cast<const __half2*>(&pv.x));
        float2 n23 = __half22float2(*reinterpret_cast<const __half2*>(&pv.y));
        float y0 = c0 + d0, y1 = c1 + d1, y2 = c2 + d2, y3 = c3 + d3;
        float w0 = fmaf(y0, n01.x, y0);
        float w1 = fmaf(y1, n01.y, y1);
        float w2 = fmaf(y2, n23.x, y2);
        float w3 = fmaf(y3, n23.y, y3);
        s = fmaf(w0, w0, fmaf(w1, w1, fmaf(w2, w2, fmaf(w3, w3, s))));
        wsh[j * 256 + tid] = make_uint2(pack_f16x2(w0, w1), pack_f16x2(w2, w3));
    }

    // per-token norm
#pragma unroll
    for (int off = 16; off > 0; off >>= 1)
        s += __shfl_xor_sync(0xffffffffu, s, off);
    if (l == 0) red[w] = s;
    __syncthreads();
    const float S = red[t * 4] + red[t * 4 + 1] + red[t * 4 + 2] + red[t * 4 + 3];
    const float inv = rsqrtf(S);   // +1e-8 on norm ~64 is 1.6e-10 rel: negligible

    // finalize |w| * inv, store
    float* o = out + (size_t)(2 * blk + t) * DTOT + dg;
#pragma unroll
    for (int j = 0; j < 8; j++) {
        uint2 pv = wsh[j * 256 + tid];
        float2 f01 = __half22float2(*reinterpret_cast<const __half2*>(&pv.x));
        float2 f23 = __half22float2(*reinterpret_cast<const __half2*>(&pv.y));
        const int qe = j * 8 + (l & 3) * 2;
        float* oj = o + qe * 64;
        __stcg(oj,      fabsf(f01.x) * inv);
        __stcg(oj + 64, fabsf(f01.y) * inv);
        __stcg(oj + 8,  fabsf(f23.x) * inv);
        __stcg(oj + 72, fabsf(f23.y) * inv);
    }

    // self-contained flag reset: last CTA clears state for the next launch.
    if (tid == 0) {
        unsigned old = atomicAdd(&g_done, 1u);
        if (old == CTAS - 1) {
            g_done = 0;
            __threadfence();
            atomicExch(&g_flag, 0);
        }
    }
}

// ------------------------- launch ------------------------------------------
extern "C" void kernel_launch(void* const* d_in, const int* in_sizes, int n_in,
                              void* d_out, int out_size)
{
    const float* x  = (const float*)d_in[0];
    const float* rx = (const float*)d_in[1];
    const float* ry = (const float*)d_in[2];
    const float* rz = (const float*)d_in[3];
    float* out = (float*)d_out;

    unsigned ka0, ka1;
    threefry2x32(0u, 42u, 0u, 0u, ka0, ka1);

    quantum_main<<<CTAS, 256>>>(x, rx, ry, rz, out, ka0, ka1);
}